// round 11
// baseline (speedup 1.0000x reference)
#include <cuda_runtime.h>
#include <cuda_fp16.h>
#include <cstdint>
#include <cstddef>

// ---------------- problem constants ----------------
static constexpr int T_TOK = 8192;
static constexpr int HID   = 4096;
static constexpr int NOUT  = 6144;   // Q(4096) + K(1024) + V(1024)
static constexpr int QS    = 4096;
static constexpr int KVS   = 1024;
static constexpr int RANK  = 16;
static constexpr int SEXT  = 128;    // per-section ext: 8 slots * 16 ranks
static constexpr int KTOT2 = HID + SEXT;  // 4224 (GEMM2 K)

// ---------------- scratch (static device memory; no allocation) ----------------
__device__ __align__(1024) __half g_xh[(size_t)T_TOK * HID];    // 67 MB
__device__ __align__(1024) __half g_wh[(size_t)NOUT * KTOT2];   // 51.9 MB
__device__ __align__(1024) __half g_ah[(size_t)3 * SEXT * HID]; //  3.1 MB (PERMUTED rows)
__device__ __align__(1024) __half g_xe[3][(size_t)T_TOK * SEXT];//  6.3 MB

// ---------------- PTX helpers (base-target only: sm_80+ features) ----------------
__device__ __forceinline__ uint32_t smem_u32(const void* p) {
    uint32_t a;
    asm("{ .reg .u64 t; cvta.to.shared.u64 t, %1; cvt.u32.u64 %0, t; }" : "=r"(a) : "l"(p));
    return a;
}

__device__ __forceinline__ void cp_async16(uint32_t dst, const void* src) {
    asm volatile("cp.async.cg.shared.global [%0], [%1], 16;\n" :: "r"(dst), "l"(src) : "memory");
}

#define CP_COMMIT()  asm volatile("cp.async.commit_group;\n" ::: "memory")
#define CP_WAIT(n)   asm volatile("cp.async.wait_group %0;\n" :: "n"(n) : "memory")

__device__ __forceinline__ uint32_t sw128(uint32_t off) {
    return off ^ ((off >> 3) & 0x70);
}

__device__ __forceinline__ void ldmatrix_x4(uint32_t* r, uint32_t addr) {
    asm volatile("ldmatrix.sync.aligned.m8n8.x4.shared.b16 {%0,%1,%2,%3}, [%4];"
                 : "=r"(r[0]), "=r"(r[1]), "=r"(r[2]), "=r"(r[3]) : "r"(addr));
}

__device__ __forceinline__ void mma16816(float* c, const uint32_t* a, uint32_t b0, uint32_t b1) {
    asm volatile("mma.sync.aligned.m16n8k16.row.col.f32.f16.f16.f32 "
                 "{%0,%1,%2,%3}, {%4,%5,%6,%7}, {%8,%9}, {%0,%1,%2,%3};"
                 : "+f"(c[0]), "+f"(c[1]), "+f"(c[2]), "+f"(c[3])
                 : "r"(a[0]), "r"(a[1]), "r"(a[2]), "r"(a[3]), "r"(b0), "r"(b1));
}

// ---------------- fused prep kernel ----------------
__device__ __forceinline__ uint4 pack8(float4 a, float4 b) {
    __half2 h0 = __floats2half2_rn(a.x, a.y);
    __half2 h1 = __floats2half2_rn(a.z, a.w);
    __half2 h2 = __floats2half2_rn(b.x, b.y);
    __half2 h3 = __floats2half2_rn(b.z, b.w);
    uint4 u;
    u.x = *reinterpret_cast<uint32_t*>(&h0);
    u.y = *reinterpret_cast<uint32_t*>(&h1);
    u.z = *reinterpret_cast<uint32_t*>(&h2);
    u.w = *reinterpret_cast<uint32_t*>(&h3);
    return u;
}

__device__ __forceinline__ void cvt8(const float* __restrict__ src, __half* __restrict__ dst,
                                     int idx, int dld) {
    const int cols8 = HID / 8;  // 512
    int r = idx / cols8, c = idx % cols8;
    const float4* p = reinterpret_cast<const float4*>(src + (size_t)r * HID + (size_t)c * 8);
    float4 f0 = p[0], f1 = p[1];
    *reinterpret_cast<uint4*>(dst + (size_t)r * dld + (size_t)c * 8) = pack8(f0, f1);
}

__global__ void __launch_bounds__(256)
prep_kernel(const float* __restrict__ x, const float* __restrict__ lA,
            const float* __restrict__ W,
            const float* __restrict__ bq, const float* __restrict__ bk,
            const float* __restrict__ bv,
            __half* __restrict__ xh, __half* __restrict__ ah, __half* __restrict__ wh) {
    int idx = blockIdx.x * blockDim.x + threadIdx.x;
    const int n1 = T_TOK * 512;       // x -> xh (fp16, ld 4096)
    const int n2 = 3 * SEXT * 512;    // lora_A -> ah (fp16, PERMUTED rows, ld 4096)
    const int n3 = NOUT * 512;        // W -> wh (fp16, ld 4224)
    const int n4 = NOUT * SEXT;       // W extension columns (one section per row)
    if (idx < n1) { cvt8(x, xh, idx, HID); return; }
    idx -= n1;
    if (idx < n2) {
        // lora_A natural row = s*48 + i*16 + r; permute to drow = i*128 + s*16 + r
        // so GEMM1 output columns land directly in per-target (i, s, r) layout.
        int row = idx >> 9, c8 = idx & 511;
        int s = row / 48, rem = row % 48;
        int i = rem >> 4, r = rem & 15;
        int drow = i * SEXT + s * RANK + r;
        const float4* p = reinterpret_cast<const float4*>(lA + (size_t)row * HID + (size_t)c8 * 8);
        float4 f0 = p[0], f1 = p[1];
        *reinterpret_cast<uint4*>(ah + (size_t)drow * HID + (size_t)c8 * 8) = pack8(f0, f1);
        return;
    }
    idx -= n2;
    if (idx < n3) { cvt8(W, wh, idx, KTOT2); return; }
    idx -= n3;
    if (idx < n4) {
        int n = idx / SEXT, j = idx % SEXT;   // j = s*16 + r
        int s = j >> 4, r = j & 15;
        float v;
        if (n < QS)            v = bq[((size_t)s * QS + n) * RANK + r];
        else if (n < QS + KVS) v = bk[((size_t)s * KVS + (n - QS)) * RANK + r];
        else                   v = bv[((size_t)s * KVS + (n - QS - KVS)) * RANK + r];
        wh[(size_t)n * KTOT2 + HID + j] = __float2half(v);
    }
}

__global__ void noop_kernel() {}

// ---------------- persistent fp16 GEMM: C[M,N] = A'[M,K] @ B[N,K]^T ----------------
// 128x128 CTA tile, 128 threads (4 warps, 2x2, warp tile 64x64), 3-stage cp.async
// (96 KB) -> 2 CTAs/SM, decoupled barriers. PERSISTENT: each CTA loops over tiles
// tau = blockIdx.x + i*gridDim.x (N-tile fast for L2 reuse). The cp.async loader
// walks a FLATTENED (tile, chunk) stream, so tile i+1's first chunks are already
// in flight / resident while tile i finishes -> no pipeline drain at boundaries
// (kills the 0.4-wave quantization tail of the fixed-grid version).
// Race-free fragment pipelining (from R10): CP_WAIT(1)+__syncthreads publishes
// stream chunk g+1 before any cross-stage frag read; next-chunk ks0 fragments are
// loaded only AFTER the barrier. (R9's pre-barrier load was a data race.)
// A is split in K: chunks [0, ncbase) from A (ld lda), the rest from a per-section
// ext buffer (ld 128) picked by the tile's output-column range (e0/e1/e2).
// FUSE: LoRA down-proj epilogue writing per-target ext buffers.
template<bool FUSE>
__global__ void __launch_bounds__(128, 2)
hgemm_kernel(const __half* __restrict__ A, int lda,
             const __half* __restrict__ B, int ldb,
             float* __restrict__ C, int ldc,
             int ncbase, int nctot, int ntn, int ntile_tot,
             const int* __restrict__ t2s, const float* __restrict__ sc,
             __half* __restrict__ e0, __half* __restrict__ e1, __half* __restrict__ e2) {
    extern __shared__ char smem[];
    constexpr int BM = 128, BN = 128, BK = 64;
    constexpr int THREADS = 128;
    constexpr int STAGE_A = BM * BK * 2;          // 16 KB
    constexpr int STAGE_B = BN * BK * 2;          // 16 KB
    constexpr int STAGE   = STAGE_A + STAGE_B;    // 32 KB
    constexpr int NSTAGE  = 3;
    constexpr int MT  = 4;                        // 16-row m-tiles per warp (64 rows)
    constexpr int NTL = 8;                        // 8-col n-tiles per warp (64 cols)
    constexpr int NPAIR = 4;                      // ldmatrix.x4 loads for B per k-step

    const int tid  = threadIdx.x;
    const int wid  = tid >> 5, lane = tid & 31;
    const int wm   = wid & 1, wn = wid >> 1;      // 2 x 2 warp grid
    const uint32_t s_base = smem_u32(smem);

    const int my_nt = (ntile_tot - (int)blockIdx.x + (int)gridDim.x - 1) / (int)gridDim.x;
    if (my_nt <= 0) return;

    const int lr   = lane & 7;   // row within 8x8 ldmatrix
    const int lsub = lane >> 3;  // which 8x8 matrix this lane's address feeds
    const int g    = lane >> 2;  // mma group row
    const int t    = lane & 3;   // mma thread-in-group

    // ---- flattened-stream loader: (li, lc) = next (tile-iter, chunk) to load ----
    int li = 0, lc = 0;
    auto do_load = [&](int stage) {
        if (li < my_nt) {
            const uint32_t sa = s_base + stage * STAGE;
            int tau = (int)blockIdx.x + li * (int)gridDim.x;
            int lm0 = (tau / ntn) * BM;
            int ln0 = (tau % ntn) * BN;
            const __half* srcA; size_t ldA;
            if (lc < ncbase) {
                srcA = A + (size_t)lm0 * lda + (size_t)lc * BK; ldA = (size_t)lda;
            } else {
                const __half* AE = (ln0 < QS) ? e0 : (ln0 < QS + KVS) ? e1 : e2;
                srcA = AE + (size_t)lm0 * SEXT + (size_t)(lc - ncbase) * BK; ldA = SEXT;
            }
            const __half* srcB = B + (size_t)ln0 * ldb + (size_t)lc * BK;
            #pragma unroll
            for (int i = 0; i < BM * 8 / THREADS; i++) {
                int id = tid + i * THREADS; int row = id >> 3, cc = id & 7;
                uint32_t off = (uint32_t)(row * 128 + cc * 16);
                cp_async16(sa + sw128(off), (const char*)srcA + row * ldA * 2 + cc * 16);
            }
            #pragma unroll
            for (int i = 0; i < BN * 8 / THREADS; i++) {
                int id = tid + i * THREADS; int row = id >> 3, cc = id & 7;
                uint32_t off = (uint32_t)(row * 128 + cc * 16);
                cp_async16(sa + STAGE_A + sw128(off), (const char*)srcB + (size_t)row * ldb * 2 + cc * 16);
            }
        }
        CP_COMMIT();                              // uniform group count, even past end
        if (++lc == nctot) { lc = 0; ++li; }
    };

    uint32_t afr[MT][4], bfr[NPAIR][4];
    auto frag_load = [&](uint32_t sa, uint32_t sb, int ks) {
        #pragma unroll
        for (int mi = 0; mi < MT; mi++) {
            int row  = wm * 64 + mi * 16 + (lsub & 1) * 8 + lr;
            int colh = ks * 16 + (lsub >> 1) * 8;
            uint32_t off = (uint32_t)(row * 128 + colh * 2);
            ldmatrix_x4(afr[mi], sa + sw128(off));
        }
        #pragma unroll
        for (int pi = 0; pi < NPAIR; pi++) {
            int row  = wn * 64 + pi * 16 + (lsub >> 1) * 8 + lr;
            int colh = ks * 16 + (lsub & 1) * 8;
            uint32_t off = (uint32_t)(row * 128 + colh * 2);
            ldmatrix_x4(bfr[pi], sb + sw128(off));
        }
    };

    // prologue: first 3 stream chunks in flight
    do_load(0); do_load(1); do_load(2);
    CP_WAIT(2);
    __syncthreads();
    frag_load(s_base, s_base + STAGE_A, 0);       // stream chunk 0, ks0

    float acc[MT][NTL][4];
    int stage_c = 0;

    for (int i = 0; i < my_nt; i++) {
        const int tau = (int)blockIdx.x + i * (int)gridDim.x;
        const int m0 = (tau / ntn) * BM;
        const int n0 = (tau % ntn) * BN;

        #pragma unroll
        for (int mi = 0; mi < MT; mi++)
            #pragma unroll
            for (int ni = 0; ni < NTL; ni++)
                #pragma unroll
                for (int q = 0; q < 4; q++) acc[mi][ni][q] = 0.f;

        for (int c = 0; c < nctot; c++) {
            const uint32_t sa = s_base + stage_c * STAGE;
            const uint32_t sb = sa + STAGE_A;
            const int stage_n = (stage_c + 1 == NSTAGE) ? 0 : stage_c + 1;
            const uint32_t sa_n = s_base + stage_n * STAGE;

            #pragma unroll
            for (int ks = 0; ks < 4; ks++) {
                #pragma unroll
                for (int mi = 0; mi < MT; mi++)
                    #pragma unroll
                    for (int ni = 0; ni < NTL; ni++)
                        mma16816(acc[mi][ni], afr[mi],
                                 bfr[ni >> 1][(ni & 1) * 2 + 0],
                                 bfr[ni >> 1][(ni & 1) * 2 + 1]);
                if (ks < 3) frag_load(sa, sb, ks + 1);
            }

            // publish stream chunk g+1 to the CTA; all reads of stage_c done
            CP_WAIT(1);
            __syncthreads();
            if (c + 1 < nctot) frag_load(sa_n, sa_n + STAGE_A, 0); // next chunk, same tile
            do_load(stage_c);                     // next stream chunk into freed stage
            stage_c = stage_n;
        }

        // ---- per-tile epilogue (next tile's chunk 0 is resident; frags loaded after) ----
        if constexpr (FUSE) {
            // LoRA down-proj: route + scale + fp16 store into per-target ext bufs.
            // Column j in [0, 384): target = j>>7, rem = j&127 = slot*16 + rank.
            #pragma unroll
            for (int mi = 0; mi < MT; mi++) {
                int r0 = m0 + wm * 64 + mi * 16 + g;
                int slot0 = t2s[r0], slot1 = t2s[r0 + 8];
                float s0 = sc[slot0], s1 = sc[slot1];
                #pragma unroll
                for (int ni = 0; ni < NTL; ni++) {
                    int j = n0 + wn * 64 + ni * 8 + 2 * t;
                    int it = j >> 7, rem = j & 127;
                    int s = rem >> 4;
                    __half* ebuf = (it == 0) ? e0 : (it == 1) ? e1 : e2;
                    __half2 h0 = (s == slot0)
                        ? __floats2half2_rn(s0 * acc[mi][ni][0], s0 * acc[mi][ni][1])
                        : __floats2half2_rn(0.f, 0.f);
                    __half2 h1 = (s == slot1)
                        ? __floats2half2_rn(s1 * acc[mi][ni][2], s1 * acc[mi][ni][3])
                        : __floats2half2_rn(0.f, 0.f);
                    *reinterpret_cast<__half2*>(ebuf + (size_t)r0 * SEXT + rem)       = h0;
                    *reinterpret_cast<__half2*>(ebuf + (size_t)(r0 + 8) * SEXT + rem) = h1;
                }
            }
        } else {
            // fp32 epilogue: streaming stores (write-once output; preserve L2 for W)
            #pragma unroll
            for (int mi = 0; mi < MT; mi++) {
                int r0 = m0 + wm * 64 + mi * 16 + g;
                #pragma unroll
                for (int ni = 0; ni < NTL; ni++) {
                    int col = n0 + wn * 64 + ni * 8 + 2 * t;
                    float2 v0 = make_float2(acc[mi][ni][0], acc[mi][ni][1]);
                    float2 v1 = make_float2(acc[mi][ni][2], acc[mi][ni][3]);
                    __stcs(reinterpret_cast<float2*>(C + (size_t)r0 * ldc + col), v0);
                    __stcs(reinterpret_cast<float2*>(C + (size_t)(r0 + 8) * ldc + col), v1);
                }
            }
        }
        // next tile's first fragments (safe: barrier for its chunk 0 already passed;
        // LDSM latency hides under the epilogue store burst above)
        if (i + 1 < my_nt)
            frag_load(s_base + stage_c * STAGE, s_base + stage_c * STAGE + STAGE_A, 0);
    }
}

// ---------------- launch ----------------
extern "C" void kernel_launch(void* const* d_in, const int* in_sizes, int n_in,
                              void* d_out, int out_size) {
    (void)in_sizes; (void)n_in; (void)out_size;
    const float* x   = (const float*)d_in[0];
    const float* W   = (const float*)d_in[1];
    const float* lA  = (const float*)d_in[2];
    const float* bq  = (const float*)d_in[3];
    const float* bk  = (const float*)d_in[4];
    const float* bv  = (const float*)d_in[5];
    const float* sc  = (const float*)d_in[6];
    const int*   t2s = (const int*)d_in[7];
    float* out = (float*)d_out;

    void *xh_p, *wh_p, *ah_p, *xe_p;
    cudaGetSymbolAddress(&xh_p, g_xh);
    cudaGetSymbolAddress(&wh_p, g_wh);
    cudaGetSymbolAddress(&ah_p, g_ah);
    cudaGetSymbolAddress(&xe_p, g_xe);
    __half* xh = (__half*)xh_p;
    __half* wh = (__half*)wh_p;
    __half* ah = (__half*)ah_p;
    __half* xe0 = (__half*)xe_p;
    __half* xe1 = xe0 + (size_t)T_TOK * SEXT;
    __half* xe2 = xe1 + (size_t)T_TOK * SEXT;

    int nsm = 148;
    cudaDeviceGetAttribute(&nsm, cudaDevAttrMultiProcessorCount, 0);

    constexpr int SMEM = 3 * (128 * 64 * 2 + 128 * 64 * 2);  // 98304 (2 CTAs/SM)
    cudaFuncSetAttribute((const void*)hgemm_kernel<true>,
                         cudaFuncAttributeMaxDynamicSharedMemorySize, SMEM);
    cudaFuncSetAttribute((const void*)hgemm_kernel<false>,
                         cudaFuncAttributeMaxDynamicSharedMemorySize, SMEM);

    // 0) alignment kernel (keeps the big GEMM on the ncu-profiled launch slot)
    noop_kernel<<<1, 32>>>();

    // 1) fused prep: x->fp16 (ld 4096), lora_A->fp16 (permuted), W->fp16 (ld 4224) + ext fill
    {
        int total = T_TOK * 512 + 3 * SEXT * 512 + NOUT * 512 + NOUT * SEXT;
        prep_kernel<<<(total + 255) / 256, 256>>>(x, lA, W, bq, bk, bv, xh, ah, wh);
    }

    // 2) down-projection GEMM (K=4096, 192 tiles -> 1 tile/CTA) + fused route/scale
    {
        int ntiles = (3 * SEXT / 128) * (T_TOK / 128);   // 192
        hgemm_kernel<true><<<ntiles, 128, SMEM>>>(
            xh, HID, ah, HID, nullptr, 0, HID / 64, HID / 64,
            3 * SEXT / 128, ntiles, t2s, sc, xe0, xe1, xe2);
    }

    // 3) main fused GEMM (persistent): out = [xh | xe_sec][T,4224] @ W'[6144,4224]^T
    {
        int ntiles = (NOUT / 128) * (T_TOK / 128);       // 3072
        int grid = 2 * nsm; if (grid > ntiles) grid = ntiles;
        hgemm_kernel<false><<<grid, 128, SMEM>>>(
            xh, HID, wh, KTOT2, out, NOUT, HID / 64, KTOT2 / 64,
            NOUT / 128, ntiles, nullptr, nullptr, xe0, xe1, xe2);
    }
}

// round 12
// speedup vs baseline: 1.0790x; 1.0790x over previous
#include <cuda_runtime.h>
#include <cuda_fp16.h>
#include <cstdint>
#include <cstddef>

// ---------------- problem constants ----------------
static constexpr int T_TOK = 8192;
static constexpr int HID   = 4096;
static constexpr int NOUT  = 6144;   // Q(4096) + K(1024) + V(1024)
static constexpr int QS    = 4096;
static constexpr int KVS   = 1024;
static constexpr int RANK  = 16;
static constexpr int SEXT  = 128;    // per-section ext: 8 slots * 16 ranks
static constexpr int KTOT2 = HID + SEXT;  // 4224 (GEMM2 K)

// ---------------- scratch (static device memory; no allocation) ----------------
__device__ __align__(1024) __half g_xh[(size_t)T_TOK * HID];    // 67 MB
__device__ __align__(1024) __half g_wh[(size_t)NOUT * KTOT2];   // 51.9 MB
__device__ __align__(1024) __half g_ah[(size_t)3 * SEXT * HID]; //  3.1 MB (PERMUTED rows)
__device__ __align__(1024) __half g_xe[3][(size_t)T_TOK * SEXT];//  6.3 MB

// ---------------- PTX helpers (base-target only: sm_80+ features) ----------------
__device__ __forceinline__ uint32_t smem_u32(const void* p) {
    uint32_t a;
    asm("{ .reg .u64 t; cvta.to.shared.u64 t, %1; cvt.u32.u64 %0, t; }" : "=r"(a) : "l"(p));
    return a;
}

__device__ __forceinline__ void cp_async16(uint32_t dst, const void* src) {
    asm volatile("cp.async.cg.shared.global [%0], [%1], 16;\n" :: "r"(dst), "l"(src) : "memory");
}

#define CP_COMMIT()  asm volatile("cp.async.commit_group;\n" ::: "memory")
#define CP_WAIT(n)   asm volatile("cp.async.wait_group %0;\n" :: "n"(n) : "memory")

__device__ __forceinline__ uint32_t sw128(uint32_t off) {
    return off ^ ((off >> 3) & 0x70);
}

__device__ __forceinline__ void ldmatrix_x4(uint32_t* r, uint32_t addr) {
    asm volatile("ldmatrix.sync.aligned.m8n8.x4.shared.b16 {%0,%1,%2,%3}, [%4];"
                 : "=r"(r[0]), "=r"(r[1]), "=r"(r[2]), "=r"(r[3]) : "r"(addr));
}

__device__ __forceinline__ void mma16816(float* c, const uint32_t* a, uint32_t b0, uint32_t b1) {
    asm volatile("mma.sync.aligned.m16n8k16.row.col.f32.f16.f16.f32 "
                 "{%0,%1,%2,%3}, {%4,%5,%6,%7}, {%8,%9}, {%0,%1,%2,%3};"
                 : "+f"(c[0]), "+f"(c[1]), "+f"(c[2]), "+f"(c[3])
                 : "r"(a[0]), "r"(a[1]), "r"(a[2]), "r"(a[3]), "r"(b0), "r"(b1));
}

// ---------------- conversion helpers ----------------
__device__ __forceinline__ uint4 pack8(float4 a, float4 b) {
    __half2 h0 = __floats2half2_rn(a.x, a.y);
    __half2 h1 = __floats2half2_rn(a.z, a.w);
    __half2 h2 = __floats2half2_rn(b.x, b.y);
    __half2 h3 = __floats2half2_rn(b.z, b.w);
    uint4 u;
    u.x = *reinterpret_cast<uint32_t*>(&h0);
    u.y = *reinterpret_cast<uint32_t*>(&h1);
    u.z = *reinterpret_cast<uint32_t*>(&h2);
    u.w = *reinterpret_cast<uint32_t*>(&h3);
    return u;
}

__device__ __forceinline__ void cvt8(const float* __restrict__ src, __half* __restrict__ dst,
                                     int idx, int dld) {
    const int cols8 = HID / 8;  // 512
    int r = idx / cols8, c = idx % cols8;
    const float4* p = reinterpret_cast<const float4*>(src + (size_t)r * HID + (size_t)c * 8);
    float4 f0 = p[0], f1 = p[1];
    *reinterpret_cast<uint4*>(dst + (size_t)r * dld + (size_t)c * 8) = pack8(f0, f1);
}

// prep1: only what GEMM1 needs (x -> xh fp16; lora_A -> ah fp16 with row permute).
// The W conversion runs concurrently with GEMM1 as worker blocks (see hgemm FUSE).
__global__ void __launch_bounds__(256)
prep1_kernel(const float* __restrict__ x, const float* __restrict__ lA,
             __half* __restrict__ xh, __half* __restrict__ ah) {
    int idx = blockIdx.x * blockDim.x + threadIdx.x;
    const int n1 = T_TOK * 512;       // x -> xh (fp16, ld 4096)
    const int n2 = 3 * SEXT * 512;    // lora_A -> ah (fp16, PERMUTED rows, ld 4096)
    if (idx < n1) { cvt8(x, xh, idx, HID); return; }
    idx -= n1;
    if (idx < n2) {
        // lora_A natural row = s*48 + i*16 + r; permute to drow = i*128 + s*16 + r
        // so GEMM1 output columns land directly in per-target (i, s, r) layout.
        int row = idx >> 9, c8 = idx & 511;
        int s = row / 48, rem = row % 48;
        int i = rem >> 4, r = rem & 15;
        int drow = i * SEXT + s * RANK + r;
        const float4* p = reinterpret_cast<const float4*>(lA + (size_t)row * HID + (size_t)c8 * 8);
        float4 f0 = p[0], f1 = p[1];
        *reinterpret_cast<uint4*>(ah + (size_t)drow * HID + (size_t)c8 * 8) = pack8(f0, f1);
    }
}

__global__ void noop_kernel() {}

// ---------------- fp16 GEMM: C[M,N] = A'[M,K] @ B[N,K]^T, fp32 accumulate ----------------
// R10 body (best known: GEMM2 864us @ tensor 81.2%): 128x128 CTA tile, 128 threads
// (4 warps 2x2, warp tile 64x64), 3-stage cp.async (96 KB) -> 2 CTAs/SM, decoupled
// barriers, RACE-FREE cross-chunk fragment pipelining (next chunk's ks0 fragments
// loaded only AFTER CP_WAIT(1)+__syncthreads; R9's pre-barrier load was a race).
// Flat 1-D grid, N-tile-fast: m0 = (tau/ntn)*128, n0 = (tau%ntn)*128.
// A is split in K: chunks [0, ncbase) from A (ld lda), rest from per-section ext
// buffer (ld 128) selected by output-column range (e0/e1/e2).
// FUSE (GEMM1): LoRA down-proj epilogue into per-target ext buffers; additionally,
// blocks with tau >= ntile_gemm are CONVERSION WORKERS that run the memory-bound
// W->fp16 + W-ext fill on the SM slots GEMM1 leaves idle (192 tiles < 296 slots).
template<bool FUSE>
__global__ void __launch_bounds__(128, 2)
hgemm_kernel(const __half* __restrict__ A, int lda,
             const __half* __restrict__ B, int ldb,
             float* __restrict__ C, int ldc,
             int ncbase, int nctot, int ntn, int ntile_gemm,
             const int* __restrict__ t2s, const float* __restrict__ sc,
             __half* __restrict__ e0, __half* __restrict__ e1, __half* __restrict__ e2,
             const float* __restrict__ Wsrc,
             const float* __restrict__ bq, const float* __restrict__ bk,
             const float* __restrict__ bv, __half* __restrict__ whdst) {
    const int tau = (int)blockIdx.x;

    if constexpr (FUSE) {
        if (tau >= ntile_gemm) {
            // -------- conversion worker: W -> wh (ld 4224) + W-ext fill --------
            const int wk   = tau - ntile_gemm;
            const int nwk  = (int)gridDim.x - ntile_gemm;
            const int tidw = wk * 128 + (int)threadIdx.x;
            const int step = nwk * 128;
            const int n3 = NOUT * 512;    // W body, uint4 granules
            for (int idx = tidw; idx < n3; idx += step) cvt8(Wsrc, whdst, idx, KTOT2);
            const int n4 = NOUT * SEXT;   // W extension columns
            for (int idx = tidw; idx < n4; idx += step) {
                int n = idx / SEXT, j = idx % SEXT;   // j = s*16 + r
                int s = j >> 4, r = j & 15;
                float v;
                if (n < QS)            v = bq[((size_t)s * QS + n) * RANK + r];
                else if (n < QS + KVS) v = bk[((size_t)s * KVS + (n - QS)) * RANK + r];
                else                   v = bv[((size_t)s * KVS + (n - QS - KVS)) * RANK + r];
                whdst[(size_t)n * KTOT2 + HID + j] = __float2half(v);
            }
            return;
        }
    }

    extern __shared__ char smem[];
    constexpr int BM = 128, BN = 128, BK = 64;
    constexpr int THREADS = 128;
    constexpr int STAGE_A = BM * BK * 2;          // 16 KB
    constexpr int STAGE_B = BN * BK * 2;          // 16 KB
    constexpr int STAGE   = STAGE_A + STAGE_B;    // 32 KB
    constexpr int NSTAGE  = 3;
    constexpr int MT  = 4;                        // 16-row m-tiles per warp (64 rows)
    constexpr int NTL = 8;                        // 8-col n-tiles per warp (64 cols)
    constexpr int NPAIR = 4;                      // ldmatrix.x4 loads for B per k-step

    const int tid  = threadIdx.x;
    const int wid  = tid >> 5, lane = tid & 31;
    const int wm   = wid & 1, wn = wid >> 1;      // 2 x 2 warp grid
    const int m0   = (tau / ntn) * BM;
    const int n0   = (tau % ntn) * BN;
    const uint32_t s_base = smem_u32(smem);

    // per-section ext pointer for A's K tail (GEMM2); unused when FUSE
    const __half* AE = nullptr;
    if constexpr (!FUSE) {
        AE = (n0 < QS) ? e0 : (n0 < QS + KVS) ? e1 : e2;
    }

    const int lr   = lane & 7;   // row within 8x8 ldmatrix
    const int lsub = lane >> 3;  // which 8x8 matrix this lane's address feeds
    const int g    = lane >> 2;  // mma group row
    const int t    = lane & 3;   // mma thread-in-group

    auto load_stage = [&](int stage, int c) {
        const uint32_t sa = s_base + stage * STAGE;
        const __half* srcA; size_t ldA;
        if (c < ncbase) { srcA = A  + (size_t)m0 * lda  + (size_t)c * BK;             ldA = (size_t)lda; }
        else            { srcA = AE + (size_t)m0 * SEXT + (size_t)(c - ncbase) * BK;  ldA = SEXT; }
        const __half* srcB = B + (size_t)n0 * ldb + (size_t)c * BK;
        #pragma unroll
        for (int i = 0; i < BM * 8 / THREADS; i++) {
            int id = tid + i * THREADS; int row = id >> 3, cc = id & 7;
            uint32_t off = (uint32_t)(row * 128 + cc * 16);
            cp_async16(sa + sw128(off), (const char*)srcA + row * ldA * 2 + cc * 16);
        }
        #pragma unroll
        for (int i = 0; i < BN * 8 / THREADS; i++) {
            int id = tid + i * THREADS; int row = id >> 3, cc = id & 7;
            uint32_t off = (uint32_t)(row * 128 + cc * 16);
            cp_async16(sa + STAGE_A + sw128(off), (const char*)srcB + (size_t)row * ldb * 2 + cc * 16);
        }
        CP_COMMIT();
    };

    #pragma unroll
    for (int s = 0; s < NSTAGE; s++) load_stage(s, s);   // prologue: 3 stages in flight

    float acc[MT][NTL][4];
    #pragma unroll
    for (int mi = 0; mi < MT; mi++)
        #pragma unroll
        for (int ni = 0; ni < NTL; ni++)
            #pragma unroll
            for (int q = 0; q < 4; q++) acc[mi][ni][q] = 0.f;

    uint32_t afr[MT][4], bfr[NPAIR][4];

    // fragment loads for k-step ks of the stage at smem offsets (sa, sb)
    auto frag_load = [&](uint32_t sa, uint32_t sb, int ks) {
        #pragma unroll
        for (int mi = 0; mi < MT; mi++) {
            int row  = wm * 64 + mi * 16 + (lsub & 1) * 8 + lr;
            int colh = ks * 16 + (lsub >> 1) * 8;
            uint32_t off = (uint32_t)(row * 128 + colh * 2);
            ldmatrix_x4(afr[mi], sa + sw128(off));
        }
        #pragma unroll
        for (int pi = 0; pi < NPAIR; pi++) {
            int row  = wn * 64 + pi * 16 + (lsub >> 1) * 8 + lr;
            int colh = ks * 16 + (lsub & 1) * 8;
            uint32_t off = (uint32_t)(row * 128 + colh * 2);
            ldmatrix_x4(bfr[pi], sb + sw128(off));
        }
    };

    // wait for chunk 0 (3 groups outstanding -> <=2 leaves chunk 0 complete)
    CP_WAIT(2);
    __syncthreads();
    frag_load(s_base, s_base + STAGE_A, 0);

    int stage_c = 0;
    for (int c = 0; c < nctot; c++) {
        const uint32_t sa = s_base + stage_c * STAGE;
        const uint32_t sb = sa + STAGE_A;
        const int stage_n = (stage_c + 1 == NSTAGE) ? 0 : stage_c + 1;
        const uint32_t sa_n = s_base + stage_n * STAGE;

        #pragma unroll
        for (int ks = 0; ks < 4; ks++) {
            // MMAs consume the fragments loaded for this ks (ks0 was preloaded
            // after the previous iteration's barrier)
            #pragma unroll
            for (int mi = 0; mi < MT; mi++)
                #pragma unroll
                for (int ni = 0; ni < NTL; ni++)
                    mma16816(acc[mi][ni], afr[mi],
                             bfr[ni >> 1][(ni & 1) * 2 + 0],
                             bfr[ni >> 1][(ni & 1) * 2 + 1]);
            if (ks < 3) frag_load(sa, sb, ks + 1);
        }

        // complete chunk c+1 in THIS thread, then barrier: all threads' waits
        // have executed -> chunk c+1 smem writes are published to the CTA, and
        // all reads of stage (c%3) are done.
        CP_WAIT(1);
        __syncthreads();
        if (c + 1 < nctot) frag_load(sa_n, sa_n + STAGE_A, 0);  // safe: post-barrier
        if (c + NSTAGE < nctot) load_stage(stage_c, c + NSTAGE);
        else CP_COMMIT();  // keep group count uniform
        stage_c = stage_n;
    }

    if constexpr (FUSE) {
        // LoRA down-proj epilogue: route + scale + fp16 store into per-target ext bufs.
        // Column j in [0, 384) is per-target order (prep permuted lora_A):
        // target = j>>7, rem = j&127 = slot*16 + rank.
        #pragma unroll
        for (int mi = 0; mi < MT; mi++) {
            int r0 = m0 + wm * 64 + mi * 16 + g;
            int slot0 = t2s[r0], slot1 = t2s[r0 + 8];
            float s0 = sc[slot0], s1 = sc[slot1];
            #pragma unroll
            for (int ni = 0; ni < NTL; ni++) {
                int j = n0 + wn * 64 + ni * 8 + 2 * t;
                int it = j >> 7, rem = j & 127;
                int s = rem >> 4;
                __half* ebuf = (it == 0) ? e0 : (it == 1) ? e1 : e2;
                __half2 h0 = (s == slot0)
                    ? __floats2half2_rn(s0 * acc[mi][ni][0], s0 * acc[mi][ni][1])
                    : __floats2half2_rn(0.f, 0.f);
                __half2 h1 = (s == slot1)
                    ? __floats2half2_rn(s1 * acc[mi][ni][2], s1 * acc[mi][ni][3])
                    : __floats2half2_rn(0.f, 0.f);
                *reinterpret_cast<__half2*>(ebuf + (size_t)r0 * SEXT + rem)       = h0;
                *reinterpret_cast<__half2*>(ebuf + (size_t)(r0 + 8) * SEXT + rem) = h1;
            }
        }
    } else {
        // fp32 epilogue: streaming stores (write-once output; don't evict the
        // L2-resident W stream that every wave re-reads)
        #pragma unroll
        for (int mi = 0; mi < MT; mi++) {
            int r0 = m0 + wm * 64 + mi * 16 + g;
            #pragma unroll
            for (int ni = 0; ni < NTL; ni++) {
                int col = n0 + wn * 64 + ni * 8 + 2 * t;
                float2 v0 = make_float2(acc[mi][ni][0], acc[mi][ni][1]);
                float2 v1 = make_float2(acc[mi][ni][2], acc[mi][ni][3]);
                __stcs(reinterpret_cast<float2*>(C + (size_t)r0 * ldc + col), v0);
                __stcs(reinterpret_cast<float2*>(C + (size_t)(r0 + 8) * ldc + col), v1);
            }
        }
    }
}

// ---------------- launch ----------------
extern "C" void kernel_launch(void* const* d_in, const int* in_sizes, int n_in,
                              void* d_out, int out_size) {
    (void)in_sizes; (void)n_in; (void)out_size;
    const float* x   = (const float*)d_in[0];
    const float* W   = (const float*)d_in[1];
    const float* lA  = (const float*)d_in[2];
    const float* bq  = (const float*)d_in[3];
    const float* bk  = (const float*)d_in[4];
    const float* bv  = (const float*)d_in[5];
    const float* sc  = (const float*)d_in[6];
    const int*   t2s = (const int*)d_in[7];
    float* out = (float*)d_out;

    void *xh_p, *wh_p, *ah_p, *xe_p;
    cudaGetSymbolAddress(&xh_p, g_xh);
    cudaGetSymbolAddress(&wh_p, g_wh);
    cudaGetSymbolAddress(&ah_p, g_ah);
    cudaGetSymbolAddress(&xe_p, g_xe);
    __half* xh = (__half*)xh_p;
    __half* wh = (__half*)wh_p;
    __half* ah = (__half*)ah_p;
    __half* xe0 = (__half*)xe_p;
    __half* xe1 = xe0 + (size_t)T_TOK * SEXT;
    __half* xe2 = xe1 + (size_t)T_TOK * SEXT;

    int nsm = 148;
    cudaDeviceGetAttribute(&nsm, cudaDevAttrMultiProcessorCount, 0);

    constexpr int SMEM = 3 * (128 * 64 * 2 + 128 * 64 * 2);  // 98304 (2 CTAs/SM)
    cudaFuncSetAttribute((const void*)hgemm_kernel<true>,
                         cudaFuncAttributeMaxDynamicSharedMemorySize, SMEM);
    cudaFuncSetAttribute((const void*)hgemm_kernel<false>,
                         cudaFuncAttributeMaxDynamicSharedMemorySize, SMEM);

    // 0) alignment kernel (keeps the big GEMM on the ncu-profiled launch slot)
    noop_kernel<<<1, 32>>>();

    // 1) prep1: x->fp16 (ld 4096) + lora_A->fp16 (permuted). W conversion is NOT
    //    here — it runs concurrently with GEMM1 below.
    {
        int total = T_TOK * 512 + 3 * SEXT * 512;
        prep1_kernel<<<(total + 255) / 256, 256>>>(x, lA, xh, ah);
    }

    // 2) down-projection GEMM (K=4096, 192 tiles) + fused route/scale epilogue,
    //    PLUS conversion workers on the idle CTA slots doing W->fp16 + ext fill.
    {
        int ntiles = (3 * SEXT / 128) * (T_TOK / 128);   // 192
        int extra = 2 * nsm - ntiles; if (extra < 32) extra = 32;
        hgemm_kernel<true><<<ntiles + extra, 128, SMEM>>>(
            xh, HID, ah, HID, nullptr, 0, HID / 64, HID / 64,
            3 * SEXT / 128, ntiles, t2s, sc, xe0, xe1, xe2,
            W, bq, bk, bv, wh);
    }

    // 3) main fused GEMM (fixed grid, R10): out = [xh | xe_sec][T,4224] @ W'[6144,4224]^T
    {
        int ntiles = (NOUT / 128) * (T_TOK / 128);       // 3072
        hgemm_kernel<false><<<ntiles, 128, SMEM>>>(
            xh, HID, wh, KTOT2, out, NOUT, HID / 64, KTOT2 / 64,
            NOUT / 128, ntiles, nullptr, nullptr, xe0, xe1, xe2,
            nullptr, nullptr, nullptr, nullptr, nullptr);
    }
}

// round 13
// speedup vs baseline: 1.1237x; 1.0414x over previous
#include <cuda_runtime.h>
#include <cuda_fp16.h>
#include <cstdint>
#include <cstddef>

// ---------------- problem constants ----------------
static constexpr int T_TOK = 8192;
static constexpr int HID   = 4096;
static constexpr int NOUT  = 6144;   // Q(4096) + K(1024) + V(1024)
static constexpr int QS    = 4096;
static constexpr int KVS   = 1024;
static constexpr int RANK  = 16;
static constexpr int SEXT  = 128;    // per-section ext: 8 slots * 16 ranks
static constexpr int KTOT2 = HID + SEXT;  // 4224 (GEMM2 K)

// ---------------- scratch (static device memory; no allocation) ----------------
__device__ __align__(1024) __half g_xh[(size_t)T_TOK * HID];    // 67 MB
__device__ __align__(1024) __half g_wh[(size_t)NOUT * KTOT2];   // 51.9 MB
__device__ __align__(1024) __half g_ah[(size_t)3 * SEXT * HID]; //  3.1 MB (PERMUTED rows)
__device__ __align__(1024) __half g_xe[3][(size_t)T_TOK * SEXT];//  6.3 MB

// ---------------- PTX helpers (base-target only: sm_80+ features) ----------------
__device__ __forceinline__ uint32_t smem_u32(const void* p) {
    uint32_t a;
    asm("{ .reg .u64 t; cvta.to.shared.u64 t, %1; cvt.u32.u64 %0, t; }" : "=r"(a) : "l"(p));
    return a;
}

__device__ __forceinline__ void cp_async16(uint32_t dst, const void* src) {
    asm volatile("cp.async.cg.shared.global [%0], [%1], 16;\n" :: "r"(dst), "l"(src) : "memory");
}

#define CP_COMMIT()  asm volatile("cp.async.commit_group;\n" ::: "memory")
#define CP_WAIT(n)   asm volatile("cp.async.wait_group %0;\n" :: "n"(n) : "memory")

__device__ __forceinline__ uint32_t sw128(uint32_t off) {
    return off ^ ((off >> 3) & 0x70);
}

__device__ __forceinline__ void ldmatrix_x4(uint32_t* r, uint32_t addr) {
    asm volatile("ldmatrix.sync.aligned.m8n8.x4.shared.b16 {%0,%1,%2,%3}, [%4];"
                 : "=r"(r[0]), "=r"(r[1]), "=r"(r[2]), "=r"(r[3]) : "r"(addr));
}

__device__ __forceinline__ void mma16816(float* c, const uint32_t* a, uint32_t b0, uint32_t b1) {
    asm volatile("mma.sync.aligned.m16n8k16.row.col.f32.f16.f16.f32 "
                 "{%0,%1,%2,%3}, {%4,%5,%6,%7}, {%8,%9}, {%0,%1,%2,%3};"
                 : "+f"(c[0]), "+f"(c[1]), "+f"(c[2]), "+f"(c[3])
                 : "r"(a[0]), "r"(a[1]), "r"(a[2]), "r"(a[3]), "r"(b0), "r"(b1));
}

// ---------------- conversion helpers ----------------
__device__ __forceinline__ uint4 pack8(float4 a, float4 b) {
    __half2 h0 = __floats2half2_rn(a.x, a.y);
    __half2 h1 = __floats2half2_rn(a.z, a.w);
    __half2 h2 = __floats2half2_rn(b.x, b.y);
    __half2 h3 = __floats2half2_rn(b.z, b.w);
    uint4 u;
    u.x = *reinterpret_cast<uint32_t*>(&h0);
    u.y = *reinterpret_cast<uint32_t*>(&h1);
    u.z = *reinterpret_cast<uint32_t*>(&h2);
    u.w = *reinterpret_cast<uint32_t*>(&h3);
    return u;
}

__device__ __forceinline__ void cvt8(const float* __restrict__ src, __half* __restrict__ dst,
                                     int idx, int dld) {
    const int cols8 = HID / 8;  // 512
    int r = idx / cols8, c = idx % cols8;
    const float4* p = reinterpret_cast<const float4*>(src + (size_t)r * HID + (size_t)c * 8);
    float4 f0 = p[0], f1 = p[1];
    *reinterpret_cast<uint4*>(dst + (size_t)r * dld + (size_t)c * 8) = pack8(f0, f1);
}

// W conversion slice: items [start, end), 128 threads. Items < n3 are 16B W-body
// granules (cvt8 into ld-4224 layout); items >= n3 are W-ext elements.
// #pragma unroll 4 -> 4 independent load/store chains in flight per thread
// (R12's serial grid-stride loop was latency-bound at ~1.2 TB/s).
__device__ __forceinline__ void wconv_slice(
    int start, int end, int tid,
    const float* __restrict__ Wsrc,
    const float* __restrict__ bq, const float* __restrict__ bk,
    const float* __restrict__ bv, __half* __restrict__ whdst) {
    const int n3 = NOUT * 512;
    #pragma unroll 4
    for (int base = start; base < end; base += 128) {
        int idx = base + tid;
        if (idx < end) {
            if (idx < n3) {
                cvt8(Wsrc, whdst, idx, KTOT2);
            } else {
                int e = idx - n3;
                int n = e / SEXT, j = e % SEXT;   // j = s*16 + r
                int s = j >> 4, r = j & 15;
                float v;
                if (n < QS)            v = bq[((size_t)s * QS + n) * RANK + r];
                else if (n < QS + KVS) v = bk[((size_t)s * KVS + (n - QS)) * RANK + r];
                else                   v = bv[((size_t)s * KVS + (n - QS - KVS)) * RANK + r];
                whdst[(size_t)n * KTOT2 + HID + j] = __float2half(v);
            }
        }
    }
}

// prep1: only what GEMM1 needs (x -> xh fp16; lora_A -> ah fp16 with row permute).
// The W conversion runs concurrently with GEMM1 (weighted split, see hgemm FUSE).
__global__ void __launch_bounds__(256)
prep1_kernel(const float* __restrict__ x, const float* __restrict__ lA,
             __half* __restrict__ xh, __half* __restrict__ ah) {
    int idx = blockIdx.x * blockDim.x + threadIdx.x;
    const int n1 = T_TOK * 512;       // x -> xh (fp16, ld 4096)
    const int n2 = 3 * SEXT * 512;    // lora_A -> ah (fp16, PERMUTED rows, ld 4096)
    if (idx < n1) { cvt8(x, xh, idx, HID); return; }
    idx -= n1;
    if (idx < n2) {
        // lora_A natural row = s*48 + i*16 + r; permute to drow = i*128 + s*16 + r
        // so GEMM1 output columns land directly in per-target (i, s, r) layout.
        int row = idx >> 9, c8 = idx & 511;
        int s = row / 48, rem = row % 48;
        int i = rem >> 4, r = rem & 15;
        int drow = i * SEXT + s * RANK + r;
        const float4* p = reinterpret_cast<const float4*>(lA + (size_t)row * HID + (size_t)c8 * 8);
        float4 f0 = p[0], f1 = p[1];
        *reinterpret_cast<uint4*>(ah + (size_t)drow * HID + (size_t)c8 * 8) = pack8(f0, f1);
    }
}

__global__ void noop_kernel() {}

// ---------------- fp16 GEMM: C[M,N] = A'[M,K] @ B[N,K]^T, fp32 accumulate ----------------
// R10 body (best known: GEMM2 864us @ tensor 81.2%): 128x128 CTA tile, 128 threads
// (4 warps 2x2, warp tile 64x64), 3-stage cp.async (96 KB) -> 2 CTAs/SM, decoupled
// barriers, RACE-FREE cross-chunk fragment pipelining (next chunk's ks0 fragments
// loaded only AFTER CP_WAIT(1)+__syncthreads; R9's pre-barrier load was a race).
// Flat 1-D grid, N-tile-fast: m0 = (tau/ntn)*128, n0 = (tau%ntn)*128.
// A is split in K: chunks [0, ncbase) from A (ld lda), rest from per-section ext
// buffer (ld 128) selected by output-column range (e0/e1/e2).
// FUSE (GEMM1): LoRA down-proj epilogue into per-target ext buffers. The W->fp16
// conversion is split across ALL blocks of this launch with static weights:
// extra blocks (tau >= ntile_gemm, weight 4) convert immediately; GEMM1 tile
// blocks (weight 1) convert a small slice after their epilogue.
template<bool FUSE>
__global__ void __launch_bounds__(128, 2)
hgemm_kernel(const __half* __restrict__ A, int lda,
             const __half* __restrict__ B, int ldb,
             float* __restrict__ C, int ldc,
             int ncbase, int nctot, int ntn, int ntile_gemm,
             const int* __restrict__ t2s, const float* __restrict__ sc,
             __half* __restrict__ e0, __half* __restrict__ e1, __half* __restrict__ e2,
             const float* __restrict__ Wsrc,
             const float* __restrict__ bq, const float* __restrict__ bk,
             const float* __restrict__ bv, __half* __restrict__ whdst) {
    const int tau = (int)blockIdx.x;

    // ---- weighted static W-conversion partition (FUSE launch only) ----
    int cv_start = 0, cv_end = 0;
    if constexpr (FUSE) {
        const int total = NOUT * 512 + NOUT * SEXT;
        const int nextra = (int)gridDim.x - ntile_gemm;
        const int units  = ntile_gemm + 4 * nextra;
        int unit = (total + units - 1) / units;
        unit = (unit + 127) & ~127;               // 128-aligned slices
        int u0 = (tau < ntile_gemm) ? tau : ntile_gemm + 4 * (tau - ntile_gemm);
        int w  = (tau < ntile_gemm) ? 1 : 4;
        cv_start = u0 * unit;
        cv_end   = cv_start + w * unit;
        if (cv_start > total) cv_start = total;
        if (cv_end   > total) cv_end   = total;

        if (tau >= ntile_gemm) {
            // extra block: convert its (big) slice immediately, then exit
            wconv_slice(cv_start, cv_end, (int)threadIdx.x, Wsrc, bq, bk, bv, whdst);
            return;
        }
    }

    extern __shared__ char smem[];
    constexpr int BM = 128, BN = 128, BK = 64;
    constexpr int THREADS = 128;
    constexpr int STAGE_A = BM * BK * 2;          // 16 KB
    constexpr int STAGE_B = BN * BK * 2;          // 16 KB
    constexpr int STAGE   = STAGE_A + STAGE_B;    // 32 KB
    constexpr int NSTAGE  = 3;
    constexpr int MT  = 4;                        // 16-row m-tiles per warp (64 rows)
    constexpr int NTL = 8;                        // 8-col n-tiles per warp (64 cols)
    constexpr int NPAIR = 4;                      // ldmatrix.x4 loads for B per k-step

    const int tid  = threadIdx.x;
    const int wid  = tid >> 5, lane = tid & 31;
    const int wm   = wid & 1, wn = wid >> 1;      // 2 x 2 warp grid
    const int m0   = (tau / ntn) * BM;
    const int n0   = (tau % ntn) * BN;
    const uint32_t s_base = smem_u32(smem);

    // per-section ext pointer for A's K tail (GEMM2); unused when FUSE
    const __half* AE = nullptr;
    if constexpr (!FUSE) {
        AE = (n0 < QS) ? e0 : (n0 < QS + KVS) ? e1 : e2;
    }

    const int lr   = lane & 7;   // row within 8x8 ldmatrix
    const int lsub = lane >> 3;  // which 8x8 matrix this lane's address feeds
    const int g    = lane >> 2;  // mma group row
    const int t    = lane & 3;   // mma thread-in-group

    auto load_stage = [&](int stage, int c) {
        const uint32_t sa = s_base + stage * STAGE;
        const __half* srcA; size_t ldA;
        if (c < ncbase) { srcA = A  + (size_t)m0 * lda  + (size_t)c * BK;             ldA = (size_t)lda; }
        else            { srcA = AE + (size_t)m0 * SEXT + (size_t)(c - ncbase) * BK;  ldA = SEXT; }
        const __half* srcB = B + (size_t)n0 * ldb + (size_t)c * BK;
        #pragma unroll
        for (int i = 0; i < BM * 8 / THREADS; i++) {
            int id = tid + i * THREADS; int row = id >> 3, cc = id & 7;
            uint32_t off = (uint32_t)(row * 128 + cc * 16);
            cp_async16(sa + sw128(off), (const char*)srcA + row * ldA * 2 + cc * 16);
        }
        #pragma unroll
        for (int i = 0; i < BN * 8 / THREADS; i++) {
            int id = tid + i * THREADS; int row = id >> 3, cc = id & 7;
            uint32_t off = (uint32_t)(row * 128 + cc * 16);
            cp_async16(sa + STAGE_A + sw128(off), (const char*)srcB + (size_t)row * ldb * 2 + cc * 16);
        }
        CP_COMMIT();
    };

    #pragma unroll
    for (int s = 0; s < NSTAGE; s++) load_stage(s, s);   // prologue: 3 stages in flight

    float acc[MT][NTL][4];
    #pragma unroll
    for (int mi = 0; mi < MT; mi++)
        #pragma unroll
        for (int ni = 0; ni < NTL; ni++)
            #pragma unroll
            for (int q = 0; q < 4; q++) acc[mi][ni][q] = 0.f;

    uint32_t afr[MT][4], bfr[NPAIR][4];

    // fragment loads for k-step ks of the stage at smem offsets (sa, sb)
    auto frag_load = [&](uint32_t sa, uint32_t sb, int ks) {
        #pragma unroll
        for (int mi = 0; mi < MT; mi++) {
            int row  = wm * 64 + mi * 16 + (lsub & 1) * 8 + lr;
            int colh = ks * 16 + (lsub >> 1) * 8;
            uint32_t off = (uint32_t)(row * 128 + colh * 2);
            ldmatrix_x4(afr[mi], sa + sw128(off));
        }
        #pragma unroll
        for (int pi = 0; pi < NPAIR; pi++) {
            int row  = wn * 64 + pi * 16 + (lsub >> 1) * 8 + lr;
            int colh = ks * 16 + (lsub & 1) * 8;
            uint32_t off = (uint32_t)(row * 128 + colh * 2);
            ldmatrix_x4(bfr[pi], sb + sw128(off));
        }
    };

    // wait for chunk 0 (3 groups outstanding -> <=2 leaves chunk 0 complete)
    CP_WAIT(2);
    __syncthreads();
    frag_load(s_base, s_base + STAGE_A, 0);

    int stage_c = 0;
    for (int c = 0; c < nctot; c++) {
        const uint32_t sa = s_base + stage_c * STAGE;
        const uint32_t sb = sa + STAGE_A;
        const int stage_n = (stage_c + 1 == NSTAGE) ? 0 : stage_c + 1;
        const uint32_t sa_n = s_base + stage_n * STAGE;

        #pragma unroll
        for (int ks = 0; ks < 4; ks++) {
            // MMAs consume the fragments loaded for this ks (ks0 was preloaded
            // after the previous iteration's barrier)
            #pragma unroll
            for (int mi = 0; mi < MT; mi++)
                #pragma unroll
                for (int ni = 0; ni < NTL; ni++)
                    mma16816(acc[mi][ni], afr[mi],
                             bfr[ni >> 1][(ni & 1) * 2 + 0],
                             bfr[ni >> 1][(ni & 1) * 2 + 1]);
            if (ks < 3) frag_load(sa, sb, ks + 1);
        }

        // complete chunk c+1 in THIS thread, then barrier: all threads' waits
        // have executed -> chunk c+1 smem writes are published to the CTA, and
        // all reads of stage (c%3) are done.
        CP_WAIT(1);
        __syncthreads();
        if (c + 1 < nctot) frag_load(sa_n, sa_n + STAGE_A, 0);  // safe: post-barrier
        if (c + NSTAGE < nctot) load_stage(stage_c, c + NSTAGE);
        else CP_COMMIT();  // keep group count uniform
        stage_c = stage_n;
    }

    if constexpr (FUSE) {
        // LoRA down-proj epilogue: route + scale + fp16 store into per-target ext bufs.
        // Column j in [0, 384) is per-target order (prep permuted lora_A):
        // target = j>>7, rem = j&127 = slot*16 + rank.
        #pragma unroll
        for (int mi = 0; mi < MT; mi++) {
            int r0 = m0 + wm * 64 + mi * 16 + g;
            int slot0 = t2s[r0], slot1 = t2s[r0 + 8];
            float s0 = sc[slot0], s1 = sc[slot1];
            #pragma unroll
            for (int ni = 0; ni < NTL; ni++) {
                int j = n0 + wn * 64 + ni * 8 + 2 * t;
                int it = j >> 7, rem = j & 127;
                int s = rem >> 4;
                __half* ebuf = (it == 0) ? e0 : (it == 1) ? e1 : e2;
                __half2 h0 = (s == slot0)
                    ? __floats2half2_rn(s0 * acc[mi][ni][0], s0 * acc[mi][ni][1])
                    : __floats2half2_rn(0.f, 0.f);
                __half2 h1 = (s == slot1)
                    ? __floats2half2_rn(s1 * acc[mi][ni][2], s1 * acc[mi][ni][3])
                    : __floats2half2_rn(0.f, 0.f);
                *reinterpret_cast<__half2*>(ebuf + (size_t)r0 * SEXT + rem)       = h0;
                *reinterpret_cast<__half2*>(ebuf + (size_t)(r0 + 8) * SEXT + rem) = h1;
            }
        }
        // tile block's (small, weight-1) W-conversion slice
        wconv_slice(cv_start, cv_end, tid, Wsrc, bq, bk, bv, whdst);
    } else {
        // fp32 epilogue: streaming stores (write-once output; don't evict the
        // L2-resident W stream that every wave re-reads)
        #pragma unroll
        for (int mi = 0; mi < MT; mi++) {
            int r0 = m0 + wm * 64 + mi * 16 + g;
            #pragma unroll
            for (int ni = 0; ni < NTL; ni++) {
                int col = n0 + wn * 64 + ni * 8 + 2 * t;
                float2 v0 = make_float2(acc[mi][ni][0], acc[mi][ni][1]);
                float2 v1 = make_float2(acc[mi][ni][2], acc[mi][ni][3]);
                __stcs(reinterpret_cast<float2*>(C + (size_t)r0 * ldc + col), v0);
                __stcs(reinterpret_cast<float2*>(C + (size_t)(r0 + 8) * ldc + col), v1);
            }
        }
    }
}

// ---------------- launch ----------------
extern "C" void kernel_launch(void* const* d_in, const int* in_sizes, int n_in,
                              void* d_out, int out_size) {
    (void)in_sizes; (void)n_in; (void)out_size;
    const float* x   = (const float*)d_in[0];
    const float* W   = (const float*)d_in[1];
    const float* lA  = (const float*)d_in[2];
    const float* bq  = (const float*)d_in[3];
    const float* bk  = (const float*)d_in[4];
    const float* bv  = (const float*)d_in[5];
    const float* sc  = (const float*)d_in[6];
    const int*   t2s = (const int*)d_in[7];
    float* out = (float*)d_out;

    void *xh_p, *wh_p, *ah_p, *xe_p;
    cudaGetSymbolAddress(&xh_p, g_xh);
    cudaGetSymbolAddress(&wh_p, g_wh);
    cudaGetSymbolAddress(&ah_p, g_ah);
    cudaGetSymbolAddress(&xe_p, g_xe);
    __half* xh = (__half*)xh_p;
    __half* wh = (__half*)wh_p;
    __half* ah = (__half*)ah_p;
    __half* xe0 = (__half*)xe_p;
    __half* xe1 = xe0 + (size_t)T_TOK * SEXT;
    __half* xe2 = xe1 + (size_t)T_TOK * SEXT;

    int nsm = 148;
    cudaDeviceGetAttribute(&nsm, cudaDevAttrMultiProcessorCount, 0);

    constexpr int SMEM = 3 * (128 * 64 * 2 + 128 * 64 * 2);  // 98304 (2 CTAs/SM)
    cudaFuncSetAttribute((const void*)hgemm_kernel<true>,
                         cudaFuncAttributeMaxDynamicSharedMemorySize, SMEM);
    cudaFuncSetAttribute((const void*)hgemm_kernel<false>,
                         cudaFuncAttributeMaxDynamicSharedMemorySize, SMEM);

    // 0) alignment kernel (keeps the big GEMM on the ncu-profiled launch slot)
    noop_kernel<<<1, 32>>>();

    // 1) prep1: x->fp16 (ld 4096) + lora_A->fp16 (permuted). W conversion is NOT
    //    here — it runs concurrently with GEMM1 below.
    {
        int total = T_TOK * 512 + 3 * SEXT * 512;
        prep1_kernel<<<(total + 255) / 256, 256>>>(x, lA, xh, ah);
    }

    // 2) down-projection GEMM (K=4096, 192 tiles) + fused route/scale epilogue,
    //    PLUS weighted W->fp16 conversion: extras (weight 4) convert from t=0,
    //    tile blocks (weight 1) convert a small slice after their epilogue.
    {
        int ntiles = (3 * SEXT / 128) * (T_TOK / 128);   // 192
        int extra = 2 * nsm - ntiles; if (extra < 32) extra = 32;
        hgemm_kernel<true><<<ntiles + extra, 128, SMEM>>>(
            xh, HID, ah, HID, nullptr, 0, HID / 64, HID / 64,
            3 * SEXT / 128, ntiles, t2s, sc, xe0, xe1, xe2,
            W, bq, bk, bv, wh);
    }

    // 3) main fused GEMM (fixed grid, R10): out = [xh | xe_sec][T,4224] @ W'[6144,4224]^T
    {
        int ntiles = (NOUT / 128) * (T_TOK / 128);       // 3072
        hgemm_kernel<false><<<ntiles, 128, SMEM>>>(
            xh, HID, wh, KTOT2, out, NOUT, HID / 64, KTOT2 / 64,
            NOUT / 128, ntiles, nullptr, nullptr, xe0, xe1, xe2,
            nullptr, nullptr, nullptr, nullptr, nullptr);
    }
}

// round 14
// speedup vs baseline: 1.1713x; 1.0424x over previous
#include <cuda_runtime.h>
#include <cuda_fp16.h>
#include <cstdint>
#include <cstddef>

// ---------------- problem constants ----------------
static constexpr int T_TOK = 8192;
static constexpr int HID   = 4096;
static constexpr int NOUT  = 6144;   // Q(4096) + K(1024) + V(1024)
static constexpr int QS    = 4096;
static constexpr int KVS   = 1024;
static constexpr int RANK  = 16;
static constexpr int SEXT  = 128;    // per-section ext: 8 slots * 16 ranks
static constexpr int KTOT2 = HID + SEXT;  // 4224 (GEMM2 K)
static constexpr int NT1   = 192;    // GEMM1 tile count (3 N x 64 M)

// ---------------- scratch (static device memory; no allocation) ----------------
__device__ __align__(1024) __half g_xh[(size_t)T_TOK * HID];    // 67 MB
__device__ __align__(1024) __half g_wh[(size_t)NOUT * KTOT2];   // 51.9 MB
__device__ __align__(1024) __half g_ah[(size_t)3 * SEXT * HID]; //  3.1 MB (PERMUTED rows)
__device__ __align__(1024) __half g_xe[3][(size_t)T_TOK * SEXT];//  6.3 MB
__device__ unsigned g_done = 0;      // GEMM1-tile completion counter (reset by prep)

// ---------------- PTX helpers (base-target only: sm_80+ features) ----------------
__device__ __forceinline__ uint32_t smem_u32(const void* p) {
    uint32_t a;
    asm("{ .reg .u64 t; cvta.to.shared.u64 t, %1; cvt.u32.u64 %0, t; }" : "=r"(a) : "l"(p));
    return a;
}

__device__ __forceinline__ void cp_async16(uint32_t dst, const void* src) {
    asm volatile("cp.async.cg.shared.global [%0], [%1], 16;\n" :: "r"(dst), "l"(src) : "memory");
}

#define CP_COMMIT()  asm volatile("cp.async.commit_group;\n" ::: "memory")
#define CP_WAIT(n)   asm volatile("cp.async.wait_group %0;\n" :: "n"(n) : "memory")

__device__ __forceinline__ uint32_t sw128(uint32_t off) {
    return off ^ ((off >> 3) & 0x70);
}

__device__ __forceinline__ void ldmatrix_x4(uint32_t* r, uint32_t addr) {
    asm volatile("ldmatrix.sync.aligned.m8n8.x4.shared.b16 {%0,%1,%2,%3}, [%4];"
                 : "=r"(r[0]), "=r"(r[1]), "=r"(r[2]), "=r"(r[3]) : "r"(addr));
}

__device__ __forceinline__ void mma16816(float* c, const uint32_t* a, uint32_t b0, uint32_t b1) {
    asm volatile("mma.sync.aligned.m16n8k16.row.col.f32.f16.f16.f32 "
                 "{%0,%1,%2,%3}, {%4,%5,%6,%7}, {%8,%9}, {%0,%1,%2,%3};"
                 : "+f"(c[0]), "+f"(c[1]), "+f"(c[2]), "+f"(c[3])
                 : "r"(a[0]), "r"(a[1]), "r"(a[2]), "r"(a[3]), "r"(b0), "r"(b1));
}

// ---------------- conversion helpers ----------------
__device__ __forceinline__ uint4 pack8(float4 a, float4 b) {
    __half2 h0 = __floats2half2_rn(a.x, a.y);
    __half2 h1 = __floats2half2_rn(a.z, a.w);
    __half2 h2 = __floats2half2_rn(b.x, b.y);
    __half2 h3 = __floats2half2_rn(b.z, b.w);
    uint4 u;
    u.x = *reinterpret_cast<uint32_t*>(&h0);
    u.y = *reinterpret_cast<uint32_t*>(&h1);
    u.z = *reinterpret_cast<uint32_t*>(&h2);
    u.w = *reinterpret_cast<uint32_t*>(&h3);
    return u;
}

__device__ __forceinline__ void cvt8(const float* __restrict__ src, __half* __restrict__ dst,
                                     int idx, int dld) {
    const int cols8 = HID / 8;  // 512
    int r = idx / cols8, c = idx % cols8;
    const float4* p = reinterpret_cast<const float4*>(src + (size_t)r * HID + (size_t)c * 8);
    float4 f0 = p[0], f1 = p[1];
    *reinterpret_cast<uint4*>(dst + (size_t)r * dld + (size_t)c * 8) = pack8(f0, f1);
}

// full prep (R10 layout): x->xh, lora_A->ah (permuted), W->wh (ld 4224), W-ext fill.
// Also resets the g_done counter for the fused GEMM launch (each graph replay).
__global__ void __launch_bounds__(256)
prep_kernel(const float* __restrict__ x, const float* __restrict__ lA,
            const float* __restrict__ W,
            const float* __restrict__ bq, const float* __restrict__ bk,
            const float* __restrict__ bv,
            __half* __restrict__ xh, __half* __restrict__ ah, __half* __restrict__ wh) {
    if (blockIdx.x == 0 && threadIdx.x == 0) g_done = 0;
    int idx = blockIdx.x * blockDim.x + threadIdx.x;
    const int n1 = T_TOK * 512;       // x -> xh (fp16, ld 4096)
    const int n2 = 3 * SEXT * 512;    // lora_A -> ah (fp16, PERMUTED rows, ld 4096)
    const int n3 = NOUT * 512;        // W -> wh (fp16, ld 4224)
    const int n4 = NOUT * SEXT;       // W extension columns (one section per row)
    if (idx < n1) { cvt8(x, xh, idx, HID); return; }
    idx -= n1;
    if (idx < n2) {
        // lora_A natural row = s*48 + i*16 + r; permute to drow = i*128 + s*16 + r
        int row = idx >> 9, c8 = idx & 511;
        int s = row / 48, rem = row % 48;
        int i = rem >> 4, r = rem & 15;
        int drow = i * SEXT + s * RANK + r;
        const float4* p = reinterpret_cast<const float4*>(lA + (size_t)row * HID + (size_t)c8 * 8);
        float4 f0 = p[0], f1 = p[1];
        *reinterpret_cast<uint4*>(ah + (size_t)drow * HID + (size_t)c8 * 8) = pack8(f0, f1);
        return;
    }
    idx -= n2;
    if (idx < n3) { cvt8(W, wh, idx, KTOT2); return; }
    idx -= n3;
    if (idx < n4) {
        int n = idx / SEXT, j = idx % SEXT;   // j = s*16 + r
        int s = j >> 4, r = j & 15;
        float v;
        if (n < QS)            v = bq[((size_t)s * QS + n) * RANK + r];
        else if (n < QS + KVS) v = bk[((size_t)s * KVS + (n - QS)) * RANK + r];
        else                   v = bv[((size_t)s * KVS + (n - QS - KVS)) * RANK + r];
        wh[(size_t)n * KTOT2 + HID + j] = __float2half(v);
    }
}

// ---------------- fused GEMM1+GEMM2 (single launch) ----------------
// R10 GEMM body (best known: 864us @ tensor 81.2%): 128x128 CTA tile, 128 threads
// (4 warps 2x2, warp tile 64x64), 3-stage cp.async (96 KB) -> 2 CTAs/SM, decoupled
// barriers, RACE-FREE cross-chunk fragment pipelining (next chunk's ks0 fragments
// loaded only AFTER CP_WAIT(1)+__syncthreads; a pre-barrier load is a data race).
// taus [0, NT1): GEMM1 tiles  (B=ah ld HID, nct=64, LoRA route/scale epilogue ->
//   per-target ext buffers, then threadfence + atomicAdd(g_done)).
// taus [NT1, ...): GEMM2 tiles (B=wh ld 4224, nct=66; chunks >= 64 read the ext
//   buffers, so before ISSUING the cp.async for chunk >= 64 the CTA spin-waits
//   g_done == NT1). Deadlock-free: all NT1 GEMM1 tiles are the lowest block ids
//   -> co-resident in wave 1 (296 slots), and they never wait.
__global__ void __launch_bounds__(128, 2)
hgemm_fused_kernel(const __half* __restrict__ A, const __half* __restrict__ B1,
                   const __half* __restrict__ B2, float* __restrict__ C,
                   const int* __restrict__ t2s, const float* __restrict__ sc,
                   __half* __restrict__ e0, __half* __restrict__ e1,
                   __half* __restrict__ e2) {
    extern __shared__ char smem[];
    constexpr int BM = 128, BN = 128, BK = 64;
    constexpr int THREADS = 128;
    constexpr int STAGE_A = BM * BK * 2;          // 16 KB
    constexpr int STAGE_B = BN * BK * 2;          // 16 KB
    constexpr int STAGE   = STAGE_A + STAGE_B;    // 32 KB
    constexpr int NSTAGE  = 3;
    constexpr int MT  = 4;                        // 16-row m-tiles per warp (64 rows)
    constexpr int NTL = 8;                        // 8-col n-tiles per warp (64 cols)
    constexpr int NPAIR = 4;                      // ldmatrix.x4 loads for B per k-step

    const int tau  = (int)blockIdx.x;
    const bool g1  = (tau < NT1);
    const int  tv  = g1 ? tau : tau - NT1;
    const int  ntn = g1 ? 3 : 48;
    const int  m0  = (tv / ntn) * BM;
    const int  n0  = (tv % ntn) * BN;
    const __half* Bp = g1 ? B1 : B2;
    const int  ldb   = g1 ? HID : KTOT2;
    const int  nctot = g1 ? 64 : 66;
    constexpr int NCBASE = 64;                    // chunks < 64 come from A (xh)

    const int tid  = threadIdx.x;
    const int wid  = tid >> 5, lane = tid & 31;
    const int wm   = wid & 1, wn = wid >> 1;      // 2 x 2 warp grid
    const uint32_t s_base = smem_u32(smem);

    // per-section ext pointer for A's K tail (GEMM2 only)
    const __half* AE = g1 ? (const __half*)nullptr
                          : ((n0 < QS) ? e0 : (n0 < QS + KVS) ? e1 : e2);

    const int lr   = lane & 7;   // row within 8x8 ldmatrix
    const int lsub = lane >> 3;  // which 8x8 matrix this lane's address feeds
    const int g    = lane >> 2;  // mma group row
    const int t    = lane & 3;   // mma thread-in-group

    bool flag_seen = g1;         // GEMM1 tiles never wait

    auto load_stage = [&](int stage, int c) {
        if (c >= NCBASE && !flag_seen) {
            // xe produced by GEMM1 tiles; acquire: volatile poll + fence
            while (*((volatile unsigned*)&g_done) < (unsigned)NT1) { }
            __threadfence();
            flag_seen = true;
        }
        const uint32_t sa = s_base + stage * STAGE;
        const __half* srcA; size_t ldA;
        if (c < NCBASE) { srcA = A  + (size_t)m0 * HID  + (size_t)c * BK;            ldA = (size_t)HID; }
        else            { srcA = AE + (size_t)m0 * SEXT + (size_t)(c - NCBASE) * BK; ldA = SEXT; }
        const __half* srcB = Bp + (size_t)n0 * ldb + (size_t)c * BK;
        #pragma unroll
        for (int i = 0; i < BM * 8 / THREADS; i++) {
            int id = tid + i * THREADS; int row = id >> 3, cc = id & 7;
            uint32_t off = (uint32_t)(row * 128 + cc * 16);
            cp_async16(sa + sw128(off), (const char*)srcA + row * ldA * 2 + cc * 16);
        }
        #pragma unroll
        for (int i = 0; i < BN * 8 / THREADS; i++) {
            int id = tid + i * THREADS; int row = id >> 3, cc = id & 7;
            uint32_t off = (uint32_t)(row * 128 + cc * 16);
            cp_async16(sa + STAGE_A + sw128(off), (const char*)srcB + (size_t)row * ldb * 2 + cc * 16);
        }
        CP_COMMIT();
    };

    #pragma unroll
    for (int s = 0; s < NSTAGE; s++) load_stage(s, s);   // prologue: 3 stages in flight

    float acc[MT][NTL][4];
    #pragma unroll
    for (int mi = 0; mi < MT; mi++)
        #pragma unroll
        for (int ni = 0; ni < NTL; ni++)
            #pragma unroll
            for (int q = 0; q < 4; q++) acc[mi][ni][q] = 0.f;

    uint32_t afr[MT][4], bfr[NPAIR][4];

    // fragment loads for k-step ks of the stage at smem offsets (sa, sb)
    auto frag_load = [&](uint32_t sa, uint32_t sb, int ks) {
        #pragma unroll
        for (int mi = 0; mi < MT; mi++) {
            int row  = wm * 64 + mi * 16 + (lsub & 1) * 8 + lr;
            int colh = ks * 16 + (lsub >> 1) * 8;
            uint32_t off = (uint32_t)(row * 128 + colh * 2);
            ldmatrix_x4(afr[mi], sa + sw128(off));
        }
        #pragma unroll
        for (int pi = 0; pi < NPAIR; pi++) {
            int row  = wn * 64 + pi * 16 + (lsub >> 1) * 8 + lr;
            int colh = ks * 16 + (lsub & 1) * 8;
            uint32_t off = (uint32_t)(row * 128 + colh * 2);
            ldmatrix_x4(bfr[pi], sb + sw128(off));
        }
    };

    // wait for chunk 0 (3 groups outstanding -> <=2 leaves chunk 0 complete)
    CP_WAIT(2);
    __syncthreads();
    frag_load(s_base, s_base + STAGE_A, 0);

    int stage_c = 0;
    for (int c = 0; c < nctot; c++) {
        const uint32_t sa = s_base + stage_c * STAGE;
        const uint32_t sb = sa + STAGE_A;
        const int stage_n = (stage_c + 1 == NSTAGE) ? 0 : stage_c + 1;
        const uint32_t sa_n = s_base + stage_n * STAGE;

        #pragma unroll
        for (int ks = 0; ks < 4; ks++) {
            // MMAs consume the fragments loaded for this ks (ks0 was preloaded
            // after the previous iteration's barrier)
            #pragma unroll
            for (int mi = 0; mi < MT; mi++)
                #pragma unroll
                for (int ni = 0; ni < NTL; ni++)
                    mma16816(acc[mi][ni], afr[mi],
                             bfr[ni >> 1][(ni & 1) * 2 + 0],
                             bfr[ni >> 1][(ni & 1) * 2 + 1]);
            if (ks < 3) frag_load(sa, sb, ks + 1);
        }

        // complete chunk c+1 in THIS thread, then barrier: all threads' waits
        // have executed -> chunk c+1 smem writes are published to the CTA, and
        // all reads of stage (c%3) are done.
        CP_WAIT(1);
        __syncthreads();
        if (c + 1 < nctot) frag_load(sa_n, sa_n + STAGE_A, 0);  // safe: post-barrier
        if (c + NSTAGE < nctot) load_stage(stage_c, c + NSTAGE);
        else CP_COMMIT();  // keep group count uniform
        stage_c = stage_n;
    }

    if (g1) {
        // LoRA down-proj epilogue: route + scale + fp16 store into per-target ext bufs.
        // Column j in [0, 384) is per-target order (prep permuted lora_A):
        // target = j>>7, rem = j&127 = slot*16 + rank.
        #pragma unroll
        for (int mi = 0; mi < MT; mi++) {
            int r0 = m0 + wm * 64 + mi * 16 + g;
            int slot0 = t2s[r0], slot1 = t2s[r0 + 8];
            float s0 = sc[slot0], s1 = sc[slot1];
            #pragma unroll
            for (int ni = 0; ni < NTL; ni++) {
                int j = n0 + wn * 64 + ni * 8 + 2 * t;
                int it = j >> 7, rem = j & 127;
                int s = rem >> 4;
                __half* ebuf = (it == 0) ? e0 : (it == 1) ? e1 : e2;
                __half2 h0 = (s == slot0)
                    ? __floats2half2_rn(s0 * acc[mi][ni][0], s0 * acc[mi][ni][1])
                    : __floats2half2_rn(0.f, 0.f);
                __half2 h1 = (s == slot1)
                    ? __floats2half2_rn(s1 * acc[mi][ni][2], s1 * acc[mi][ni][3])
                    : __floats2half2_rn(0.f, 0.f);
                *reinterpret_cast<__half2*>(ebuf + (size_t)r0 * SEXT + rem)       = h0;
                *reinterpret_cast<__half2*>(ebuf + (size_t)(r0 + 8) * SEXT + rem) = h1;
            }
        }
        // release: xe visible, then count this tile done
        __threadfence();
        __syncthreads();
        if (tid == 0) atomicAdd(&g_done, 1u);
    } else {
        // fp32 epilogue: streaming stores (write-once output; don't evict the
        // L2-resident W stream that every wave re-reads)
        #pragma unroll
        for (int mi = 0; mi < MT; mi++) {
            int r0 = m0 + wm * 64 + mi * 16 + g;
            #pragma unroll
            for (int ni = 0; ni < NTL; ni++) {
                int col = n0 + wn * 64 + ni * 8 + 2 * t;
                float2 v0 = make_float2(acc[mi][ni][0], acc[mi][ni][1]);
                float2 v1 = make_float2(acc[mi][ni][2], acc[mi][ni][3]);
                __stcs(reinterpret_cast<float2*>(C + (size_t)r0 * NOUT + col), v0);
                __stcs(reinterpret_cast<float2*>(C + (size_t)(r0 + 8) * NOUT + col), v1);
            }
        }
    }
}

// ---------------- launch ----------------
extern "C" void kernel_launch(void* const* d_in, const int* in_sizes, int n_in,
                              void* d_out, int out_size) {
    (void)in_sizes; (void)n_in; (void)out_size;
    const float* x   = (const float*)d_in[0];
    const float* W   = (const float*)d_in[1];
    const float* lA  = (const float*)d_in[2];
    const float* bq  = (const float*)d_in[3];
    const float* bk  = (const float*)d_in[4];
    const float* bv  = (const float*)d_in[5];
    const float* sc  = (const float*)d_in[6];
    const int*   t2s = (const int*)d_in[7];
    float* out = (float*)d_out;

    void *xh_p, *wh_p, *ah_p, *xe_p;
    cudaGetSymbolAddress(&xh_p, g_xh);
    cudaGetSymbolAddress(&wh_p, g_wh);
    cudaGetSymbolAddress(&ah_p, g_ah);
    cudaGetSymbolAddress(&xe_p, g_xe);
    __half* xh = (__half*)xh_p;
    __half* wh = (__half*)wh_p;
    __half* ah = (__half*)ah_p;
    __half* xe0 = (__half*)xe_p;
    __half* xe1 = xe0 + (size_t)T_TOK * SEXT;
    __half* xe2 = xe1 + (size_t)T_TOK * SEXT;

    constexpr int SMEM = 3 * (128 * 64 * 2 + 128 * 64 * 2);  // 98304 (2 CTAs/SM)
    cudaFuncSetAttribute((const void*)hgemm_fused_kernel,
                         cudaFuncAttributeMaxDynamicSharedMemorySize, SMEM);

    // 1) full prep (R10): x->fp16, lora_A->fp16 (permuted), W->fp16 + ext fill;
    //    also resets g_done for this replay.
    {
        int total = T_TOK * 512 + 3 * SEXT * 512 + NOUT * 512 + NOUT * SEXT;
        prep_kernel<<<(total + 255) / 256, 256>>>(x, lA, W, bq, bk, bv, xh, ah, wh);
    }

    // 2) fused GEMM1 + GEMM2 in one launch:
    //    taus [0,192): a[T,384] = xh @ ah^T with route/scale epilogue -> xe bufs
    //    taus [192, 3264): out = [xh | xe_sec][T,4224] @ W'[6144,4224]^T
    {
        int grid = NT1 + (NOUT / 128) * (T_TOK / 128);   // 192 + 3072
        hgemm_fused_kernel<<<grid, 128, SMEM>>>(
            xh, ah, wh, out, t2s, sc, xe0, xe1, xe2);
    }
}